// round 6
// baseline (speedup 1.0000x reference)
#include <cuda_runtime.h>

#define BB 16
#define CC 512
#define NN 2048
#define MAXH 70
#define MAXW 40
#define HW 2800           // MAXH*MAXW
#define HW4 700           // HW/4
#define CH 4              // channels per block
#define NTHR 512
#define NWARP (NTHR / 32)
#define PTS_PER_THR (NN / NTHR)   // 4
#define BIGV 1000000
#define SMEM_BYTES (CH * NN * 4 + HW * 4)   // 32768 + 11200 = 43968

__global__ void __launch_bounds__(NTHR, 4)
fused_kernel(const float* __restrict__ features,   // [B, C, N]
             const float* __restrict__ backend,    // [C]
             const int*   __restrict__ ys,         // [B, N]
             const int*   __restrict__ xs,         // [B, N]
             float*       __restrict__ out)        // [B, C, MAXH, MAXW]
{
    extern __shared__ float s_dyn[];
    float* s_feat = s_dyn;                          // CH * NN floats
    int*   s_map  = (int*)(s_dyn + CH * NN);        // HW ints
    __shared__ int s_mny[NWARP], s_mxy[NWARP], s_mnx[NWARP], s_mxx[NWARP];
    __shared__ int s_par[5];

    const int b   = blockIdx.y;
    const int c0  = blockIdx.x * CH;
    const int tid = threadIdx.x;
    const int wid = tid >> 5;
    const int lid = tid & 31;

    // ---- 1. stage CH feature rows into smem (coalesced float4, issued
    //          first so DRAM latency overlaps prologue compute) ----
    const float4* fbase4 = (const float4*)(features + ((size_t)b * CC + c0) * NN);
    float4* s_feat4 = (float4*)s_feat;
    #pragma unroll
    for (int k = 0; k < (CH * NN / 4) / NTHR; k++)   // 4 iters
        s_feat4[tid + k * NTHR] = __ldg(&fbase4[tid + k * NTHR]);

    // ---- 2. load coords + bbox reduce ----
    const int* y = ys + b * NN;
    const int* x = xs + b * NN;
    int ry[PTS_PER_THR], rx[PTS_PER_THR];
    int mny = BIGV, mxy = -BIGV, mnx = BIGV, mxx = -BIGV;
    #pragma unroll
    for (int k = 0; k < PTS_PER_THR; k++) {
        int n  = tid + k * NTHR;
        int yv = __ldg(&y[n]);
        int xv = __ldg(&x[n]);
        ry[k] = yv; rx[k] = xv;
        if (yv > -1) {
            mny = min(mny, yv); mxy = max(mxy, yv);
            mnx = min(mnx, xv); mxx = max(mxx, xv);
        }
    }
    #pragma unroll
    for (int o = 16; o > 0; o >>= 1) {
        mny = min(mny, __shfl_xor_sync(0xffffffffu, mny, o));
        mxy = max(mxy, __shfl_xor_sync(0xffffffffu, mxy, o));
        mnx = min(mnx, __shfl_xor_sync(0xffffffffu, mnx, o));
        mxx = max(mxx, __shfl_xor_sync(0xffffffffu, mxx, o));
    }
    if (lid == 0) { s_mny[wid] = mny; s_mxy[wid] = mxy; s_mnx[wid] = mnx; s_mxx[wid] = mxx; }

    // ---- 3. init map ----
    for (int i = tid; i < HW; i += NTHR) s_map[i] = -1;
    __syncthreads();

    // ---- 4. finalize params (warp 0) ----
    if (wid == 0) {
        mny = (lid < NWARP) ? s_mny[lid] : BIGV;
        mxy = (lid < NWARP) ? s_mxy[lid] : -BIGV;
        mnx = (lid < NWARP) ? s_mnx[lid] : BIGV;
        mxx = (lid < NWARP) ? s_mxx[lid] : -BIGV;
        #pragma unroll
        for (int o = 8; o > 0; o >>= 1) {
            mny = min(mny, __shfl_xor_sync(0xffffffffu, mny, o));
            mxy = max(mxy, __shfl_xor_sync(0xffffffffu, mxy, o));
            mnx = min(mnx, __shfl_xor_sync(0xffffffffu, mnx, o));
            mxx = max(mxx, __shfl_xor_sync(0xffffffffu, mxx, o));
        }
        if (lid == 0) {
            int h = mxy - mny + 1;
            int w = mxx - mnx + 1;
            int trans = (w > h) ? 1 : 0;
            int H2 = trans ? w : h;
            int W2 = trans ? h : w;
            int hd = H2 - MAXH;
            int wd = W2 - MAXW;
            // numerators positive in both branches -> C div == floor div
            int sy = (hd > 0) ? -((hd + 1) / 2) : ((1 - hd) / 2);
            int sx = (wd > 0) ? -((wd + 1) / 2) : ((1 - wd) / 2);
            s_par[0] = mny; s_par[1] = mnx; s_par[2] = sy; s_par[3] = sx; s_par[4] = trans;
        }
    }
    __syncthreads();

    const int min_y = s_par[0], min_x = s_par[1];
    const int sy = s_par[2], sx = s_par[3], trans = s_par[4];

    // ---- 5. scatter into smem map (NumPy wrap for negatives;
    //          last-write-wins by point order -> atomicMax) ----
    #pragma unroll
    for (int k = 0; k < PTS_PER_THR; k++) {
        int yv = ry[k];
        if (yv > -1) {
            int xv = rx[k];
            int dy = yv - min_y;
            int dx = xv - min_x;
            int yy = trans ? dx : dy;
            int xx = trans ? dy : dx;
            int oy = yy + sy;
            int ox = xx + sx;
            if (oy < 0) oy += MAXH;
            if (ox < 0) ox += MAXW;
            if (oy >= 0 && oy < MAXH && ox >= 0 && ox < MAXW)
                atomicMax(&s_map[oy * MAXW + ox], tid + k * NTHR);
        }
    }
    __syncthreads();   // also fences the feature staging stores

    // ---- 6. gather from smem, coalesced float4 writes ----
    float back[CH];
    #pragma unroll
    for (int cc = 0; cc < CH; cc++) back[cc] = __ldg(&backend[c0 + cc]);

    float* obase = out + ((size_t)b * CC + c0) * HW;
    const int4* s_map4 = (const int4*)s_map;

    for (int q = tid; q < HW4; q += NTHR) {
        int4 im = s_map4[q];          // one LDS.128 for 4 pixel indices
        int p = q * 4;
        #pragma unroll
        for (int cc = 0; cc < CH; cc++) {
            const float* srow = s_feat + cc * NN;
            float4 v;
            v.x = (im.x >= 0) ? srow[im.x] : back[cc];
            v.y = (im.y >= 0) ? srow[im.y] : back[cc];
            v.z = (im.z >= 0) ? srow[im.z] : back[cc];
            v.w = (im.w >= 0) ? srow[im.w] : back[cc];
            *reinterpret_cast<float4*>(obase + cc * HW + p) = v;
        }
    }
}

extern "C" void kernel_launch(void* const* d_in, const int* in_sizes, int n_in,
                              void* d_out, int out_size) {
    const float* features = nullptr;
    const float* backend  = nullptr;
    const int*   ys       = nullptr;
    const int*   xs       = nullptr;
    for (int i = 0; i < n_in; i++) {
        if (in_sizes[i] == BB * CC * NN)      features = (const float*)d_in[i];
        else if (in_sizes[i] == CC)           backend  = (const float*)d_in[i];
        else if (in_sizes[i] == BB * NN) {
            if (!ys) ys = (const int*)d_in[i];
            else     xs = (const int*)d_in[i];
        }
    }
    float* out = (float*)d_out;

    cudaFuncSetAttribute(fused_kernel,
                         cudaFuncAttributeMaxDynamicSharedMemorySize, SMEM_BYTES);
    dim3 grid(CC / CH, BB);   // 128 x 16 = 2048 blocks
    fused_kernel<<<grid, NTHR, SMEM_BYTES>>>(features, backend, ys, xs, out);
}